// round 4
// baseline (speedup 1.0000x reference)
#include <cuda_runtime.h>
#include <math.h>

// Problem constants
#define C_DIM 64
#define K_DIM 512
#define N_SIG 65536
#define SPARSITY 5

// Output layout (z_st [64,64,32,32], loss scalar, coeffs [512,65536]) concatenated
#define ZST_SIZE   4194304
#define LOSS_IDX   4194304
#define COEF_BASE  4194305
#define OUT_TOTAL  37748737

// Main kernel config
#define TPB 256
#define SIG_PER_BLK 32
#define NBLK 2048

// Shared layout (floats). REC aliases CORR (safe: per-warp column-exclusive,
// REC writes to a column happen only after that column's CORR reads).
#define S_OFF    0            // [64][36]  signals, padded for v4/v2 + banks
#define S_PITCH  36
#define CORR_OFF 2304         // [512][33] correlations
#define CORR_PITCH 33
#define REC_OFF  CORR_OFF     // [64][33]  reconstruction staging (alias)
#define REC_PITCH 33
#define LOSS_OFF (CORR_OFF+16896)
#define SMEM_FLOATS (LOSS_OFF+1)
#define SMEM_BYTES  (SMEM_FLOATS*4)

// Packed f32x2 FMA (Blackwell; ptxas never auto-fuses — PTX only)
#define FMA2(acc, a, b) \
    asm("fma.rn.f32x2 %0, %1, %2, %0;" : "+l"(acc) : "l"(a), "l"(b))
#define PACK_BCAST(dst, s) \
    asm("mov.b64 %0, {%1, %1};" : "=l"(dst) : "r"(__float_as_uint(s)))
#define UNPACK2(lo, hi, v) \
    asm("mov.b64 {%0, %1}, %2;" : "=r"(lo), "=r"(hi) : "l"(v))

__device__ float g_G[K_DIM*K_DIM];   // Gram matrix DtD [512][512]
__device__ float g_Dt[K_DIM*C_DIM];  // D transposed   [512][64]

// ---------------------------------------------------------------------------
// G = D^T D, Dt = D^T. D is [64][512] row-major. One block per Gram row.
__global__ void gram_kernel(const float* __restrict__ D) {
    __shared__ float col[C_DIM];
    int b = blockIdx.x;     // atom index (row of G)
    int t = threadIdx.x;    // 512 threads
    if (t < C_DIM) {
        float v = D[t * K_DIM + b];
        col[t] = v;
        g_Dt[b * C_DIM + t] = v;
    }
    __syncthreads();
    float s = 0.f;
#pragma unroll
    for (int i = 0; i < C_DIM; i++)
        s += col[i] * __ldg(&D[i * K_DIM + t]);
    g_G[b * K_DIM + t] = s;
}

// ---------------------------------------------------------------------------
// Fused: init_corr GEMM + batch OMP + outputs (coeffs, recon, loss partial)
__global__ void __launch_bounds__(TPB)
omp_kernel(const float* __restrict__ z, const float* __restrict__ D,
           float* __restrict__ out) {
    extern __shared__ float smem[];
    float* S    = smem + S_OFF;
    float* CORR = smem + CORR_OFF;
    float* REC  = smem + REC_OFF;
    float* sLoss = smem + LOSS_OFF;

    const int tid = threadIdx.x;
    const int b = blockIdx.x;
    const int r  = b & 63;                 // channel residue of signal index
    const int q0 = (b >> 6) * SIG_PER_BLK; // spatial base

    if (tid == 0) *sLoss = 0.f;

    // ---- Load signal tile: S[i][j] = z_e_flat[i*65536 + r*1024 + q0+j] ----
#pragma unroll
    for (int it = 0; it < 8; it++) {
        int idx = tid + it * TPB;          // 0..2047
        int i = idx >> 5, j = idx & 31;
        S[i * S_PITCH + j] = z[(size_t)i * 65536 + (size_t)r * 1024 + q0 + j];
    }
    __syncthreads();

    // ---- Phase 1: CORR[k][j] = sum_i D[i,k] * S[i][j]  (packed f32x2) ----
    {
        unsigned long long A0[16], A1[16];
#pragma unroll
        for (int t = 0; t < 16; t++) { A0[t] = 0ull; A1[t] = 0ull; }
#pragma unroll 2
        for (int i = 0; i < 64; i++) {
            float d0 = __ldg(&D[i * K_DIM + tid]);
            float d1 = __ldg(&D[i * K_DIM + tid + 256]);
            unsigned long long d0p, d1p;
            PACK_BCAST(d0p, d0);
            PACK_BCAST(d1p, d1);
            const ulonglong2* Sr = (const ulonglong2*)(S + i * S_PITCH);
#pragma unroll
            for (int c2 = 0; c2 < 8; c2++) {
                ulonglong2 sv = Sr[c2];   // 4 floats = 2 packed pairs
                FMA2(A0[c2*2+0], d0p, sv.x);
                FMA2(A0[c2*2+1], d0p, sv.y);
                FMA2(A1[c2*2+0], d1p, sv.x);
                FMA2(A1[c2*2+1], d1p, sv.y);
            }
        }
#pragma unroll
        for (int t = 0; t < 16; t++) {
            unsigned lo, hi;
            UNPACK2(lo, hi, A0[t]);
            CORR[(size_t)tid * CORR_PITCH + 2*t]     = __uint_as_float(lo);
            CORR[(size_t)tid * CORR_PITCH + 2*t + 1] = __uint_as_float(hi);
            UNPACK2(lo, hi, A1[t]);
            CORR[(size_t)(tid + 256) * CORR_PITCH + 2*t]     = __uint_as_float(lo);
            CORR[(size_t)(tid + 256) * CORR_PITCH + 2*t + 1] = __uint_as_float(hi);
        }
    }
    __syncthreads();

    // ---- Phase 2: warp-per-signal OMP (each warp: 4 signals) ----
    const int w = tid >> 5;
    const int l = tid & 31;
    float lossAcc = 0.f;

    for (int sig = 0; sig < 4; sig++) {
        const int j = w * 4 + sig;
        // corr spread across lanes: lane l holds atoms k = l + 32m
        float c[16];
#pragma unroll
        for (int m = 0; m < 16; m++) c[m] = CORR[(size_t)(l + 32 * m) * CORR_PITCH + j];

        unsigned mask = 0xFFFFu;   // per-lane availability of its 16 slots
        float Lm[15];              // packed lower-tri Cholesky
        int   I[5];
        float xs[5], bbv[5], xv[5];
        float grow[4][16];         // cached Gram rows of selected atoms
#pragma unroll
        for (int jj = 0; jj < 5; jj++) xs[jj] = 0.f;
        Lm[0] = 1.f;

#pragma unroll
        for (int k = 1; k <= 5; k++) {
            // --- masked argmax |corr| via REDUX (tie -> lowest index) ---
            // abs-bits as uint preserve float ordering for non-negatives.
            unsigned best = 0u;
#pragma unroll
            for (int m = 0; m < 16; m++) {
                unsigned a = __float_as_uint(c[m]) & 0x7FFFFFFFu;
                a = ((mask >> m) & 1u) ? a : 0u;
                best = best > a ? best : a;
            }
            unsigned gmax = __reduce_max_sync(0xFFFFFFFFu, best);
            unsigned cand = 0xFFFFu;
#pragma unroll
            for (int m = 0; m < 16; m++) {
                unsigned a = __float_as_uint(c[m]) & 0x7FFFFFFFu;
                bool ok = (((mask >> m) & 1u) != 0u) && (a == gmax);
                unsigned idx = (unsigned)(l + 32 * m);
                if (ok && idx < cand) cand = idx;
            }
            const int gidx = (int)__reduce_min_sync(0xFFFFFFFFu, cand);

            const int mo = gidx >> 5, lo = gidx & 31;
            float vsel = c[0];
#pragma unroll
            for (int m = 1; m < 16; m++) if (m == mo) vsel = c[m];
            const float ck = __shfl_sync(0xffffffffu, vsel, lo);
            if (l == lo) mask &= ~(1u << mo);

            // --- g_prev[jj] = G[I_jj, k_hat]  (warp-uniform loads) ---
            float gp[4];
#pragma unroll
            for (int jj = 0; jj < k - 1; jj++)
                gp[jj] = g_G[(size_t)I[jj] * K_DIM + gidx];

            // --- b[k-1] = init_corr[k_hat] = corr[k_hat] + sum xs_j * gp_j ---
            {
                float bk = ck;
#pragma unroll
                for (int jj = 0; jj < k - 1; jj++) bk += xs[jj] * gp[jj];
                bbv[k - 1] = bk;
            }

            // --- progressive Cholesky update ---
            if (k > 1) {
                float wv[4];
#pragma unroll
                for (int rr = 0; rr < k - 1; rr++) {
                    float t = gp[rr];
#pragma unroll
                    for (int cc = 0; cc < rr; cc++) t -= Lm[rr*(rr+1)/2 + cc] * wv[cc];
                    wv[rr] = t / Lm[rr*(rr+1)/2 + rr];
                }
                float s2 = 0.f;
#pragma unroll
                for (int rr = 0; rr < k - 1; rr++) s2 += wv[rr] * wv[rr];
                float wbr = sqrtf(1.f - s2);
#pragma unroll
                for (int cc = 0; cc < k - 1; cc++) Lm[(k-1)*k/2 + cc] = wv[cc];
                Lm[(k-1)*k/2 + (k-1)] = wbr;
            }
            I[k - 1] = gidx;

            // --- solve L L^T x = b (sizes <= 5, replicated in all lanes) ---
            float y[5];
#pragma unroll
            for (int rr = 0; rr < k; rr++) {
                float t = bbv[rr];
#pragma unroll
                for (int cc = 0; cc < rr; cc++) t -= Lm[rr*(rr+1)/2 + cc] * y[cc];
                y[rr] = t / Lm[rr*(rr+1)/2 + rr];
            }
#pragma unroll
            for (int rr = k - 1; rr >= 0; rr--) {
                float t = y[rr];
#pragma unroll
                for (int cc = rr + 1; cc < k; cc++) t -= Lm[cc*(cc+1)/2 + rr] * xv[cc];
                xv[rr] = t / Lm[rr*(rr+1)/2 + rr];
            }

            // --- incremental corr update: c -= (x_new - x_old) . G rows ---
            if (k < 5) {
#pragma unroll
                for (int m = 0; m < 16; m++)
                    grow[k - 1][m] = g_G[(size_t)gidx * K_DIM + l + 32 * m];
#pragma unroll
                for (int jj = 0; jj < k; jj++) {
                    float dx = xv[jj] - xs[jj];
#pragma unroll
                    for (int m = 0; m < 16; m++) c[m] -= dx * grow[jj][m];
                    xs[jj] = xv[jj];
                }
            } else {
#pragma unroll
                for (int jj = 0; jj < 5; jj++) xs[jj] = xv[jj];
            }
        }

        const int n = ((q0 + j) << 6) + r;   // global signal index

        // coeffs (sparse scatter; region pre-zeroed by memset)
        if (l == 0) {
#pragma unroll
            for (int jj = 0; jj < 5; jj++)
                out[(size_t)COEF_BASE + (size_t)I[jj] * 65536 + n] = xs[jj];
        }

        // reconstruction: rec_i = sum_j xs_j * D[i, I_j]  (Dt coalesced)
        float r0 = 0.f, r1 = 0.f;
#pragma unroll
        for (int jj = 0; jj < 5; jj++) {
            const float* dt = &g_Dt[(size_t)I[jj] * C_DIM];
            r0 += xs[jj] * dt[l];
            r1 += xs[jj] * dt[l + 32];
        }
        REC[l * REC_PITCH + j]        = r0;
        REC[(l + 32) * REC_PITCH + j] = r1;

        float e0 = r0 - S[l * S_PITCH + j];
        float e1 = r1 - S[(l + 32) * S_PITCH + j];
        lossAcc += e0 * e0 + e1 * e1;
    }

    // reduce loss within warp, accumulate to block
#pragma unroll
    for (int off = 16; off > 0; off >>= 1)
        lossAcc += __shfl_xor_sync(0xffffffffu, lossAcc, off);
    if (l == 0) atomicAdd(sLoss, lossAcc);
    __syncthreads();

    // coalesced z_st writes: out[i*65536 + r*1024 + q0 + j] = rec
#pragma unroll
    for (int it = 0; it < 8; it++) {
        int idx = tid + it * TPB;
        int i = idx >> 5, j = idx & 31;
        out[(size_t)i * 65536 + (size_t)r * 1024 + q0 + j] = REC[i * REC_PITCH + j];
    }
    if (tid == 0)
        atomicAdd(&out[LOSS_IDX], (*sLoss) * (1.25f / 4194304.f));
}

// ---------------------------------------------------------------------------
extern "C" void kernel_launch(void* const* d_in, const int* in_sizes, int n_in,
                              void* d_out, int out_size) {
    const float* z = (const float*)d_in[0];   // z_e [64,64,32,32]
    const float* D = (const float*)d_in[1];   // dictionary [64,512]
    float* out = (float*)d_out;

    cudaFuncSetAttribute(omp_kernel, cudaFuncAttributeMaxDynamicSharedMemorySize,
                         SMEM_BYTES);

    // zero loss + coeffs region (z_st region fully overwritten by omp_kernel)
    cudaMemsetAsync(out + LOSS_IDX, 0, (size_t)(OUT_TOTAL - LOSS_IDX) * sizeof(float));
    gram_kernel<<<K_DIM, K_DIM>>>(D);
    omp_kernel<<<NBLK, TPB, SMEM_BYTES>>>(z, D, out);
}

// round 5
// speedup vs baseline: 1.4622x; 1.4622x over previous
#include <cuda_runtime.h>
#include <math.h>

// Problem constants
#define C_DIM 64
#define K_DIM 512
#define N_SIG 65536
#define SPARSITY 5

// Output layout (z_st [64,64,32,32], loss scalar, coeffs [512,65536]) concatenated
#define ZST_SIZE   4194304
#define LOSS_IDX   4194304
#define COEF_BASE  4194305
#define OUT_TOTAL  37748737

// Main kernel config
#define TPB 256
#define SIG_PER_BLK 32
#define NBLK 2048

// Shared layout (floats). REC aliases CORR (safe: per-warp column-exclusive,
// REC writes to a column happen only after that column's CORR reads).
#define S_OFF    0            // [64][36]  signals, padded for v4/v2 + banks
#define S_PITCH  36
#define CORR_OFF 2304         // [512][33] correlations
#define CORR_PITCH 33
#define REC_OFF  CORR_OFF     // [64][33]  reconstruction staging (alias)
#define REC_PITCH 33
#define LOSS_OFF (CORR_OFF+16896)
#define SMEM_FLOATS (LOSS_OFF+1)
#define SMEM_BYTES  (SMEM_FLOATS*4)

// Packed f32x2 FMA (Blackwell; ptxas never auto-fuses — PTX only)
#define FMA2(acc, a, b) \
    asm("fma.rn.f32x2 %0, %1, %2, %0;" : "+l"(acc) : "l"(a), "l"(b))
#define PACK_BCAST(dst, s) \
    asm("mov.b64 %0, {%1, %1};" : "=l"(dst) : "r"(__float_as_uint(s)))
#define UNPACK2(lo, hi, v) \
    asm("mov.b64 {%0, %1}, %2;" : "=r"(lo), "=r"(hi) : "l"(v))

__device__ float g_G[K_DIM*K_DIM];   // Gram matrix DtD [512][512]
__device__ float g_Dt[K_DIM*C_DIM];  // D transposed   [512][64]

// ---------------------------------------------------------------------------
// G = D^T D, Dt = D^T. D is [64][512] row-major. One block per Gram row.
__global__ void gram_kernel(const float* __restrict__ D) {
    __shared__ float col[C_DIM];
    int b = blockIdx.x;     // atom index (row of G)
    int t = threadIdx.x;    // 512 threads
    if (t < C_DIM) {
        float v = D[t * K_DIM + b];
        col[t] = v;
        g_Dt[b * C_DIM + t] = v;
    }
    __syncthreads();
    float s = 0.f;
#pragma unroll
    for (int i = 0; i < C_DIM; i++)
        s += col[i] * __ldg(&D[i * K_DIM + t]);
    g_G[b * K_DIM + t] = s;
}

// ---------------------------------------------------------------------------
// Fused: init_corr GEMM + batch OMP + outputs (coeffs, recon, loss partial)
// __launch_bounds__(TPB, 2): force regs<=128 so 2 CTAs/SM fit (R4 regression
// root cause: 147 regs -> 1 CTA/SM -> issue 37.6%).
__global__ void __launch_bounds__(TPB, 2)
omp_kernel(const float* __restrict__ z, const float* __restrict__ D,
           float* __restrict__ out) {
    extern __shared__ float smem[];
    float* S    = smem + S_OFF;
    float* CORR = smem + CORR_OFF;
    float* REC  = smem + REC_OFF;
    float* sLoss = smem + LOSS_OFF;

    const int tid = threadIdx.x;
    const int b = blockIdx.x;
    const int r  = b & 63;                 // channel residue of signal index
    const int q0 = (b >> 6) * SIG_PER_BLK; // spatial base

    if (tid == 0) *sLoss = 0.f;

    // ---- Load signal tile: S[i][j] = z_e_flat[i*65536 + r*1024 + q0+j] ----
#pragma unroll
    for (int it = 0; it < 8; it++) {
        int idx = tid + it * TPB;          // 0..2047
        int i = idx >> 5, j = idx & 31;
        S[i * S_PITCH + j] = z[(size_t)i * 65536 + (size_t)r * 1024 + q0 + j];
    }
    __syncthreads();

    // ---- Phase 1: CORR[k][j] = sum_i D[i,k] * S[i][j]  (packed f32x2) ----
    {
        unsigned long long A0[16], A1[16];
#pragma unroll
        for (int t = 0; t < 16; t++) { A0[t] = 0ull; A1[t] = 0ull; }
#pragma unroll 2
        for (int i = 0; i < 64; i++) {
            float d0 = __ldg(&D[i * K_DIM + tid]);
            float d1 = __ldg(&D[i * K_DIM + tid + 256]);
            unsigned long long d0p, d1p;
            PACK_BCAST(d0p, d0);
            PACK_BCAST(d1p, d1);
            const ulonglong2* Sr = (const ulonglong2*)(S + i * S_PITCH);
#pragma unroll
            for (int c2 = 0; c2 < 8; c2++) {
                ulonglong2 sv = Sr[c2];   // 4 floats = 2 packed pairs
                FMA2(A0[c2*2+0], d0p, sv.x);
                FMA2(A0[c2*2+1], d0p, sv.y);
                FMA2(A1[c2*2+0], d1p, sv.x);
                FMA2(A1[c2*2+1], d1p, sv.y);
            }
        }
#pragma unroll
        for (int t = 0; t < 16; t++) {
            unsigned lo, hi;
            UNPACK2(lo, hi, A0[t]);
            CORR[(size_t)tid * CORR_PITCH + 2*t]     = __uint_as_float(lo);
            CORR[(size_t)tid * CORR_PITCH + 2*t + 1] = __uint_as_float(hi);
            UNPACK2(lo, hi, A1[t]);
            CORR[(size_t)(tid + 256) * CORR_PITCH + 2*t]     = __uint_as_float(lo);
            CORR[(size_t)(tid + 256) * CORR_PITCH + 2*t + 1] = __uint_as_float(hi);
        }
    }
    __syncthreads();

    // ---- Phase 2: warp-per-signal OMP (each warp: 4 signals) ----
    const int w = tid >> 5;
    const int l = tid & 31;
    float lossAcc = 0.f;

    for (int sig = 0; sig < 4; sig++) {
        const int j = w * 4 + sig;
        // corr spread across lanes: lane l holds atoms k = l + 32m
        float c[16];
#pragma unroll
        for (int m = 0; m < 16; m++) c[m] = CORR[(size_t)(l + 32 * m) * CORR_PITCH + j];

        unsigned mask = 0xFFFFu;   // per-lane availability of its 16 slots
        float Lm[15];              // packed lower-tri Cholesky
        int   I[5];
        float xs[5], bbv[5], xv[5];
        float grow[4][16];         // cached Gram rows of selected atoms
#pragma unroll
        for (int jj = 0; jj < 5; jj++) xs[jj] = 0.f;
        Lm[0] = 1.f;

#pragma unroll
        for (int k = 1; k <= 5; k++) {
            // --- masked argmax |corr| via REDUX (tie -> lowest index) ---
            // abs-bits as uint preserve float ordering for non-negatives.
            unsigned best = 0u;
#pragma unroll
            for (int m = 0; m < 16; m++) {
                unsigned a = __float_as_uint(c[m]) & 0x7FFFFFFFu;
                a = ((mask >> m) & 1u) ? a : 0u;
                best = best > a ? best : a;
            }
            unsigned gmax = __reduce_max_sync(0xFFFFFFFFu, best);
            unsigned cand = 0xFFFFu;
#pragma unroll
            for (int m = 0; m < 16; m++) {
                unsigned a = __float_as_uint(c[m]) & 0x7FFFFFFFu;
                bool ok = (((mask >> m) & 1u) != 0u) && (a == gmax);
                unsigned idx = (unsigned)(l + 32 * m);
                if (ok && idx < cand) cand = idx;
            }
            const int gidx = (int)__reduce_min_sync(0xFFFFFFFFu, cand);

            const int mo = gidx >> 5, lo = gidx & 31;
            float vsel = c[0];
#pragma unroll
            for (int m = 1; m < 16; m++) if (m == mo) vsel = c[m];
            const float ck = __shfl_sync(0xffffffffu, vsel, lo);
            if (l == lo) mask &= ~(1u << mo);

            // --- g_prev[jj] = G[I_jj, k_hat]  (warp-uniform loads) ---
            float gp[4];
#pragma unroll
            for (int jj = 0; jj < k - 1; jj++)
                gp[jj] = g_G[(size_t)I[jj] * K_DIM + gidx];

            // --- b[k-1] = init_corr[k_hat] = corr[k_hat] + sum xs_j * gp_j ---
            {
                float bk = ck;
#pragma unroll
                for (int jj = 0; jj < k - 1; jj++) bk += xs[jj] * gp[jj];
                bbv[k - 1] = bk;
            }

            // --- progressive Cholesky update ---
            if (k > 1) {
                float wv[4];
#pragma unroll
                for (int rr = 0; rr < k - 1; rr++) {
                    float t = gp[rr];
#pragma unroll
                    for (int cc = 0; cc < rr; cc++) t -= Lm[rr*(rr+1)/2 + cc] * wv[cc];
                    wv[rr] = t / Lm[rr*(rr+1)/2 + rr];
                }
                float s2 = 0.f;
#pragma unroll
                for (int rr = 0; rr < k - 1; rr++) s2 += wv[rr] * wv[rr];
                float wbr = sqrtf(1.f - s2);
#pragma unroll
                for (int cc = 0; cc < k - 1; cc++) Lm[(k-1)*k/2 + cc] = wv[cc];
                Lm[(k-1)*k/2 + (k-1)] = wbr;
            }
            I[k - 1] = gidx;

            // --- solve L L^T x = b (sizes <= 5, replicated in all lanes) ---
            float y[5];
#pragma unroll
            for (int rr = 0; rr < k; rr++) {
                float t = bbv[rr];
#pragma unroll
                for (int cc = 0; cc < rr; cc++) t -= Lm[rr*(rr+1)/2 + cc] * y[cc];
                y[rr] = t / Lm[rr*(rr+1)/2 + rr];
            }
#pragma unroll
            for (int rr = k - 1; rr >= 0; rr--) {
                float t = y[rr];
#pragma unroll
                for (int cc = rr + 1; cc < k; cc++) t -= Lm[cc*(cc+1)/2 + rr] * xv[cc];
                xv[rr] = t / Lm[rr*(rr+1)/2 + rr];
            }

            // --- incremental corr update: c -= (x_new - x_old) . G rows ---
            if (k < 5) {
#pragma unroll
                for (int m = 0; m < 16; m++)
                    grow[k - 1][m] = g_G[(size_t)gidx * K_DIM + l + 32 * m];
#pragma unroll
                for (int jj = 0; jj < k; jj++) {
                    float dx = xv[jj] - xs[jj];
#pragma unroll
                    for (int m = 0; m < 16; m++) c[m] -= dx * grow[jj][m];
                    xs[jj] = xv[jj];
                }
            } else {
#pragma unroll
                for (int jj = 0; jj < 5; jj++) xs[jj] = xv[jj];
            }
        }

        const int n = ((q0 + j) << 6) + r;   // global signal index

        // coeffs (sparse scatter; region pre-zeroed by memset)
        if (l == 0) {
#pragma unroll
            for (int jj = 0; jj < 5; jj++)
                out[(size_t)COEF_BASE + (size_t)I[jj] * 65536 + n] = xs[jj];
        }

        // reconstruction: rec_i = sum_j xs_j * D[i, I_j]  (Dt coalesced)
        float r0 = 0.f, r1 = 0.f;
#pragma unroll
        for (int jj = 0; jj < 5; jj++) {
            const float* dt = &g_Dt[(size_t)I[jj] * C_DIM];
            r0 += xs[jj] * dt[l];
            r1 += xs[jj] * dt[l + 32];
        }
        REC[l * REC_PITCH + j]        = r0;
        REC[(l + 32) * REC_PITCH + j] = r1;

        float e0 = r0 - S[l * S_PITCH + j];
        float e1 = r1 - S[(l + 32) * S_PITCH + j];
        lossAcc += e0 * e0 + e1 * e1;
    }

    // reduce loss within warp, accumulate to block
#pragma unroll
    for (int off = 16; off > 0; off >>= 1)
        lossAcc += __shfl_xor_sync(0xffffffffu, lossAcc, off);
    if (l == 0) atomicAdd(sLoss, lossAcc);
    __syncthreads();

    // coalesced z_st writes: out[i*65536 + r*1024 + q0 + j] = rec
#pragma unroll
    for (int it = 0; it < 8; it++) {
        int idx = tid + it * TPB;
        int i = idx >> 5, j = idx & 31;
        out[(size_t)i * 65536 + (size_t)r * 1024 + q0 + j] = REC[i * REC_PITCH + j];
    }
    if (tid == 0)
        atomicAdd(&out[LOSS_IDX], (*sLoss) * (1.25f / 4194304.f));
}

// ---------------------------------------------------------------------------
extern "C" void kernel_launch(void* const* d_in, const int* in_sizes, int n_in,
                              void* d_out, int out_size) {
    const float* z = (const float*)d_in[0];   // z_e [64,64,32,32]
    const float* D = (const float*)d_in[1];   // dictionary [64,512]
    float* out = (float*)d_out;

    cudaFuncSetAttribute(omp_kernel, cudaFuncAttributeMaxDynamicSharedMemorySize,
                         SMEM_BYTES);

    // zero loss + coeffs region (z_st region fully overwritten by omp_kernel)
    cudaMemsetAsync(out + LOSS_IDX, 0, (size_t)(OUT_TOTAL - LOSS_IDX) * sizeof(float));
    gram_kernel<<<K_DIM, K_DIM>>>(D);
    omp_kernel<<<NBLK, TPB, SMEM_BYTES>>>(z, D, out);
}